// round 7
// baseline (speedup 1.0000x reference)
#include <cuda_runtime.h>
#include <cuda_fp16.h>
#include <cstdint>

#define NROWS   8192
#define DMODEL  1024
#define NKEYS   2048
#define NBH     32

__device__ __half g_Qh [NROWS * DMODEL];
__device__ __half g_Kh [NROWS * DMODEL];
__device__ __half g_Wqh[DMODEL * DMODEL];
__device__ __half g_Wkh[DMODEL * DMODEL];
__device__ __half g_Wvh[DMODEL * DMODEL];
__device__ __half g_Woh[DMODEL * DMODEL];
__device__ __half g_qh [NROWS * DMODEL];
__device__ __half g_kh [NROWS * DMODEL];
__device__ __half g_vh [NROWS * DMODEL];
__device__ __half g_x0h[NROWS * DMODEL];
__device__ float  g_att[NROWS * DMODEL];
__device__ float  g_x0f[NROWS * DMODEL];

__device__ __forceinline__ uint32_t h2u(__half2 h) {
    uint32_t u;
    asm("mov.b32 %0, %1;" : "=r"(u) : "r"(*(uint32_t*)&h));
    return u;
}
__device__ __forceinline__ void ldsm4(uint32_t a[4], uint32_t addr) {
    asm volatile("ldmatrix.sync.aligned.m8n8.x4.shared.b16 {%0,%1,%2,%3}, [%4];"
                 : "=r"(a[0]), "=r"(a[1]), "=r"(a[2]), "=r"(a[3]) : "r"(addr));
}
__device__ __forceinline__ void ldsm4t(uint32_t a[4], uint32_t addr) {
    asm volatile("ldmatrix.sync.aligned.m8n8.x4.trans.shared.b16 {%0,%1,%2,%3}, [%4];"
                 : "=r"(a[0]), "=r"(a[1]), "=r"(a[2]), "=r"(a[3]) : "r"(addr));
}
__device__ __forceinline__ void mma_h(float* c, const uint32_t a[4], uint32_t b0, uint32_t b1) {
    asm volatile("mma.sync.aligned.m16n8k16.row.col.f32.f16.f16.f32 "
                 "{%0,%1,%2,%3}, {%4,%5,%6,%7}, {%8,%9}, {%0,%1,%2,%3};"
                 : "+f"(c[0]), "+f"(c[1]), "+f"(c[2]), "+f"(c[3])
                 : "r"(a[0]), "r"(a[1]), "r"(a[2]), "r"(a[3]), "r"(b0), "r"(b1));
}
__device__ __forceinline__ void cp16(uint32_t dst, const void* src) {
    asm volatile("cp.async.ca.shared.global [%0], [%1], 16;\n" :: "r"(dst), "l"(src));
}
#define CP_COMMIT() asm volatile("cp.async.commit_group;\n")
#define CP_WAIT1()  asm volatile("cp.async.wait_group 1;\n")
#define CP_WAIT3()  asm volatile("cp.async.wait_group 3;\n")

__device__ __forceinline__ float warpSum(float v) {
    #pragma unroll
    for (int o = 16; o; o >>= 1) v += __shfl_xor_sync(0xFFFFFFFFu, v, o);
    return v;
}
__device__ __forceinline__ float quadMax(float v) {
    v = fmaxf(v, __shfl_xor_sync(0xFFFFFFFFu, v, 1));
    v = fmaxf(v, __shfl_xor_sync(0xFFFFFFFFu, v, 2));
    return v;
}
__device__ __forceinline__ float quadSum(float v) {
    v += __shfl_xor_sync(0xFFFFFFFFu, v, 1);
    v += __shfl_xor_sync(0xFFFFFFFFu, v, 2);
    return v;
}

// ---------------- batched fp32 -> fp16 ----------------
struct ConvArgs { const float* s[4]; __half* d[4]; };

__global__ __launch_bounds__(256)
void conv_f2h(ConvArgs ca, int n)
{
    const float* s = ca.s[blockIdx.y];
    __half*      d = ca.d[blockIdx.y];
    int i = (blockIdx.x * 256 + threadIdx.x) * 4;
    if (i < n) {
        float4 v = *(const float4*)(s + i);
        __half2* o = (__half2*)(d + i);
        o[0] = __floats2half2_rn(v.x, v.y);
        o[1] = __floats2half2_rn(v.z, v.w);
    }
}

// ---------------------------------------------------------------------------
// fp16 GEMM C = epi(A @ B^T), batched over blockIdx.z (pointer arrays).
// A[8192,1024]h, B[1024,1024]h (n,k row-major). BM=BN=128 BK=64, 8 warps.
// EPI 0: half C = acc + bias.  EPI 3: float C = Res + relu(acc + bias).
// ---------------------------------------------------------------------------
struct GemmArgs {
    const __half* A[3];
    const __half* B[3];
    void*         C[3];
    const float*  bias[3];
    const float*  Res;
};

template<int EPI>
__global__ __launch_bounds__(256, 2)
void gemm_h(GemmArgs ga)
{
    extern __shared__ char smc[];
    const uint32_t smA = (uint32_t)__cvta_generic_to_shared(smc);
    const uint32_t smB = smA + 32768;

    const int z = blockIdx.z;
    const __half* __restrict__ A = ga.A[z];
    const __half* __restrict__ B = ga.B[z];
    void* Cv = ga.C[z];
    const float* __restrict__ bias = ga.bias[z];
    const float* __restrict__ Res = ga.Res;

    const int m0 = blockIdx.y * 128, n0 = blockIdx.x * 128;
    const int tid = threadIdx.x, warp = tid >> 5, lane = tid & 31;
    const int wm = (warp >> 2) * 64, wn = (warp & 3) * 32;
    const int g = lane >> 2, tg = lane & 3;
    const uint32_t l7 = lane & 7, lb3 = (lane >> 3) & 1, lb4 = (uint32_t)lane >> 4;

    float acc[4][4][4];
    #pragma unroll
    for (int i = 0; i < 4; i++)
        #pragma unroll
        for (int j = 0; j < 4; j++)
            #pragma unroll
            for (int e = 0; e < 4; e++) acc[i][j][e] = 0.f;

    auto stage = [&](int s, int k0) {
        #pragma unroll
        for (int i = 0; i < 4; i++) {
            int idx = tid + i * 256;
            uint32_t row = idx >> 3, c = idx & 7;
            uint32_t d = s * 16384 + row * 128 + ((c ^ (row & 7)) * 16);
            cp16(smA + d, A + (long)(m0 + row) * DMODEL + k0 + c * 8);
            cp16(smB + d, B + (long)(n0 + row) * DMODEL + k0 + c * 8);
        }
    };
    stage(0, 0);  CP_COMMIT();
    stage(1, 64); CP_COMMIT();

    for (int kt = 0; kt < 16; kt++) {
        CP_WAIT1();
        __syncthreads();
        const uint32_t sa = smA + (kt & 1) * 16384;
        const uint32_t sb = smB + (kt & 1) * 16384;
        #pragma unroll
        for (int ks = 0; ks < 4; ks++) {
            uint32_t af[4][4], bf[2][4];
            #pragma unroll
            for (int mi = 0; mi < 4; mi++) {
                uint32_t row = wm + mi * 16 + lb3 * 8 + l7;
                uint32_t cc  = ks * 2 + lb4;
                ldsm4(af[mi], sa + row * 128 + ((cc ^ (row & 7)) * 16));
            }
            #pragma unroll
            for (int nj = 0; nj < 2; nj++) {
                uint32_t row = wn + nj * 16 + lb4 * 8 + l7;
                uint32_t cc  = ks * 2 + lb3;
                ldsm4(bf[nj], sb + row * 128 + ((cc ^ (row & 7)) * 16));
            }
            #pragma unroll
            for (int mi = 0; mi < 4; mi++)
                #pragma unroll
                for (int nf = 0; nf < 4; nf++)
                    mma_h(acc[mi][nf], af[mi], bf[nf >> 1][(nf & 1) * 2],
                          bf[nf >> 1][(nf & 1) * 2 + 1]);
        }
        __syncthreads();
        if (kt < 14) stage(kt & 1, (kt + 2) * 64);
        CP_COMMIT();
    }

    #pragma unroll
    for (int mi = 0; mi < 4; mi++) {
        #pragma unroll
        for (int nf = 0; nf < 4; nf++) {
            int r = m0 + wm + mi * 16 + g;
            int c = n0 + wn + nf * 8 + 2 * tg;
            float b0 = bias[c], b1 = bias[c + 1];
            if (EPI == 0) {
                __half* C = (__half*)Cv;
                *(__half2*)(C + (long)r * DMODEL + c) =
                    __floats2half2_rn(acc[mi][nf][0] + b0, acc[mi][nf][1] + b1);
                *(__half2*)(C + (long)(r + 8) * DMODEL + c) =
                    __floats2half2_rn(acc[mi][nf][2] + b0, acc[mi][nf][3] + b1);
            } else {
                float* C = (float*)Cv;
                float2 v0, v1;
                v0.x = fmaxf(acc[mi][nf][0] + b0, 0.f) + Res[(long)r * DMODEL + c];
                v0.y = fmaxf(acc[mi][nf][1] + b1, 0.f) + Res[(long)r * DMODEL + c + 1];
                v1.x = fmaxf(acc[mi][nf][2] + b0, 0.f) + Res[(long)(r + 8) * DMODEL + c];
                v1.y = fmaxf(acc[mi][nf][3] + b1, 0.f) + Res[(long)(r + 8) * DMODEL + c + 1];
                *(float2*)(C + (long)r * DMODEL + c) = v0;
                *(float2*)(C + (long)(r + 8) * DMODEL + c) = v1;
            }
        }
    }
}

// ---------------------------------------------------------------------------
// fp16 flash: CTA = one (b,h), 128 q-rows; 32 tiles of 64 keys, K/V cp.async
// QUAD-buffered (4 stages). Warp owns 16 rows; P stays in registers.
// smem: Q [0,34816) | K 4x17408 [34816,104448) | V 4x17408 [104448,174080)
// ---------------------------------------------------------------------------
__global__ __launch_bounds__(256, 1)
void flash_h(const __half* __restrict__ qb, const __half* __restrict__ kb,
             const __half* __restrict__ vb, float* __restrict__ att)
{
    extern __shared__ char smc[];
    const uint32_t smQ = (uint32_t)__cvta_generic_to_shared(smc);
    const uint32_t smK = smQ + 34816;
    const uint32_t smV = smQ + 104448;

    const int bh = blockIdx.y, zb = bh >> 3, zh = bh & 7;
    const long base = (long)zb * (NKEYS * DMODEL) + zh * 128;
    const __half* qp = qb + base + (long)blockIdx.x * 128 * DMODEL;
    const __half* kp = kb + base;
    const __half* vp = vb + base;
    float*        op = att + base + (long)blockIdx.x * 128 * DMODEL;

    const int tid = threadIdx.x, warp = tid >> 5, lane = tid & 31;
    const int g = lane >> 2, tg = lane & 3;
    const int wr = warp * 16;
    const uint32_t l7 = lane & 7, lb3 = (lane >> 3) & 1, lb4 = (uint32_t)lane >> 4;
    const float isq = 0.088388347648318447f;

    // stage Q (part of commit group 0)
    #pragma unroll
    for (int i = 0; i < 8; i++) {
        int idx = tid + i * 256;
        uint32_t r = idx >> 4, c = idx & 15;
        cp16(smQ + r * 272 + c * 16, qp + (long)r * DMODEL + c * 8);
    }
    auto stage = [&](int s, int jt) {
        #pragma unroll
        for (int i = 0; i < 4; i++) {
            int idx = tid + i * 256;
            uint32_t r = idx >> 4, c = idx & 15;
            const long go = (long)(jt * 64 + r) * DMODEL + c * 8;
            uint32_t d = s * 17408 + r * 272 + c * 16;
            cp16(smK + d, kp + go);
            cp16(smV + d, vp + go);
        }
    };
    stage(0, 0); CP_COMMIT();
    stage(1, 1); CP_COMMIT();
    stage(2, 2); CP_COMMIT();
    stage(3, 3); CP_COMMIT();

    float o[16][4];
    #pragma unroll
    for (int f = 0; f < 16; f++)
        #pragma unroll
        for (int e = 0; e < 4; e++) o[f][e] = 0.f;
    float m0 = -1e30f, m1 = -1e30f, l0 = 0.f, l1 = 0.f;

    for (int j = 0; j < 32; j++) {
        CP_WAIT3();
        __syncthreads();
        const uint32_t sk = smK + (j & 3) * 17408;
        const uint32_t sv = smV + (j & 3) * 17408;

        // ---- S = Q K^T : 16 rows x 64 keys, 8 k16 steps ----
        float s[8][4];
        #pragma unroll
        for (int t = 0; t < 8; t++)
            #pragma unroll
            for (int e = 0; e < 4; e++) s[t][e] = 0.f;
        #pragma unroll
        for (int ks = 0; ks < 8; ks++) {
            uint32_t qa[4];
            {
                uint32_t row = wr + lb3 * 8 + l7;
                ldsm4(qa, smQ + row * 272 + (ks * 2 + lb4) * 16);
            }
            #pragma unroll
            for (int nt = 0; nt < 4; nt++) {
                uint32_t kf[4];
                uint32_t row = nt * 16 + lb4 * 8 + l7;
                ldsm4(kf, sk + row * 272 + (ks * 2 + lb3) * 16);
                mma_h(s[nt * 2],     qa, kf[0], kf[1]);
                mma_h(s[nt * 2 + 1], qa, kf[2], kf[3]);
            }
        }

        // ---- online softmax (rows wr+g, wr+g+8) ----
        float tm0 = -1e30f, tm1 = -1e30f;
        #pragma unroll
        for (int t = 0; t < 8; t++) {
            s[t][0] *= isq; s[t][1] *= isq; s[t][2] *= isq; s[t][3] *= isq;
            tm0 = fmaxf(tm0, fmaxf(s[t][0], s[t][1]));
            tm1 = fmaxf(tm1, fmaxf(s[t][2], s[t][3]));
        }
        tm0 = quadMax(tm0); tm1 = quadMax(tm1);
        float mn0 = fmaxf(m0, tm0), mn1 = fmaxf(m1, tm1);
        float sc0 = __expf(m0 - mn0), sc1 = __expf(m1 - mn1);
        m0 = mn0; m1 = mn1;
        float ls0 = 0.f, ls1 = 0.f;
        uint32_t ah[8][2];
        #pragma unroll
        for (int t = 0; t < 8; t++) {
            s[t][0] = __expf(s[t][0] - mn0);
            s[t][1] = __expf(s[t][1] - mn0);
            s[t][2] = __expf(s[t][2] - mn1);
            s[t][3] = __expf(s[t][3] - mn1);
            ls0 += s[t][0] + s[t][1];
            ls1 += s[t][2] + s[t][3];
            ah[t][0] = h2u(__floats2half2_rn(s[t][0], s[t][1]));
            ah[t][1] = h2u(__floats2half2_rn(s[t][2], s[t][3]));
        }
        l0 = l0 * sc0 + ls0;
        l1 = l1 * sc1 + ls1;
        #pragma unroll
        for (int f = 0; f < 16; f++) {
            o[f][0] *= sc0; o[f][1] *= sc0;
            o[f][2] *= sc1; o[f][3] *= sc1;
        }

        // ---- O += P V : 4 k16 steps over keys, 16 n8 tiles over d ----
        #pragma unroll
        for (int kv = 0; kv < 4; kv++) {
            uint32_t pa[4] = { ah[2*kv][0], ah[2*kv][1], ah[2*kv+1][0], ah[2*kv+1][1] };
            #pragma unroll
            for (int nt2 = 0; nt2 < 8; nt2++) {
                uint32_t vf[4];
                uint32_t row = kv * 16 + lb3 * 8 + l7;
                ldsm4t(vf, sv + row * 272 + (nt2 * 2 + lb4) * 16);
                mma_h(o[nt2 * 2],     pa, vf[0], vf[1]);
                mma_h(o[nt2 * 2 + 1], pa, vf[2], vf[3]);
            }
        }
        __syncthreads();
        if (j < 28) stage(j & 3, j + 4);
        CP_COMMIT();
    }

    // ---- epilogue: out = q + O / l ----
    l0 = quadSum(l0); l1 = quadSum(l1);
    const float i0 = 1.f / l0, i1 = 1.f / l1;
    const int r0 = wr + g, r1 = wr + g + 8;
    #pragma unroll
    for (int nf = 0; nf < 16; nf++) {
        int c = nf * 8 + 2 * tg;
        float2 q0 = __half22float2(*(const __half2*)(qp + (long)r0 * DMODEL + c));
        float2 q1 = __half22float2(*(const __half2*)(qp + (long)r1 * DMODEL + c));
        *(float2*)(op + (long)r0 * DMODEL + c) =
            make_float2(q0.x + o[nf][0] * i0, q0.y + o[nf][1] * i0);
        *(float2*)(op + (long)r1 * DMODEL + c) =
            make_float2(q1.x + o[nf][2] * i1, q1.y + o[nf][3] * i1);
    }
}

// ---------------------------------------------------------------------------
// LayerNorm (rows of 1024). WH: also emit half copy.
// ---------------------------------------------------------------------------
template<bool WH>
__global__ __launch_bounds__(256)
void ln_kernel(const float* __restrict__ X, float* __restrict__ Y,
               __half* __restrict__ Yh,
               const float* __restrict__ gam, const float* __restrict__ bet)
{
    const float* x = X + (size_t)blockIdx.x * DMODEL;
    float*       y = Y + (size_t)blockIdx.x * DMODEL;
    __half*      yh = WH ? (Yh + (size_t)blockIdx.x * DMODEL) : nullptr;
    const int tid = threadIdx.x;
    float v[4];
    float s = 0.f, sq = 0.f;
    #pragma unroll
    for (int i = 0; i < 4; i++) {
        v[i] = x[i * 256 + tid];
        s  += v[i];
        sq += v[i] * v[i];
    }
    s  = warpSum(s);
    sq = warpSum(sq);
    __shared__ float a1[8], a2[8];
    if ((tid & 31) == 0) { a1[tid >> 5] = s; a2[tid >> 5] = sq; }
    __syncthreads();
    float S1 = ((a1[0] + a1[1]) + (a1[2] + a1[3])) + ((a1[4] + a1[5]) + (a1[6] + a1[7]));
    float S2 = ((a2[0] + a2[1]) + (a2[2] + a2[3])) + ((a2[4] + a2[5]) + (a2[6] + a2[7]));
    float mu  = S1 * (1.f / DMODEL);
    float var = S2 * (1.f / DMODEL) - mu * mu;
    float rs  = rsqrtf(var + 1e-5f);
    #pragma unroll
    for (int i = 0; i < 4; i++) {
        int c = i * 256 + tid;
        float r = (v[i] - mu) * rs * gam[c] + bet[c];
        y[c] = r;
        if (WH) yh[c] = __float2half_rn(r);
    }
}

// ---------------------------------------------------------------------------
extern "C" void kernel_launch(void* const* d_in, const int* in_sizes, int n_in,
                              void* d_out, int out_size)
{
    (void)in_sizes; (void)n_in; (void)out_size;
    const float* Q  = (const float*)d_in[0];
    const float* K_ = (const float*)d_in[1];
    const float* Wq = (const float*)d_in[2];
    const float* bq = (const float*)d_in[3];
    const float* Wk = (const float*)d_in[4];
    const float* bk = (const float*)d_in[5];
    const float* Wv = (const float*)d_in[6];
    const float* bv = (const float*)d_in[7];
    const float* Wo = (const float*)d_in[8];
    const float* bo = (const float*)d_in[9];
    const float* g0 = (const float*)d_in[10];
    const float* b0 = (const float*)d_in[11];
    const float* g1 = (const float*)d_in[12];
    const float* b1 = (const float*)d_in[13];
    float* out = (float*)d_out;

    __half *Qh, *Kh, *Wqh, *Wkh, *Wvh, *Woh, *qh, *kh, *vh, *x0h;
    float *att, *x0f;
    cudaGetSymbolAddress((void**)&Qh,  g_Qh);
    cudaGetSymbolAddress((void**)&Kh,  g_Kh);
    cudaGetSymbolAddress((void**)&Wqh, g_Wqh);
    cudaGetSymbolAddress((void**)&Wkh, g_Wkh);
    cudaGetSymbolAddress((void**)&Wvh, g_Wvh);
    cudaGetSymbolAddress((void**)&Woh, g_Woh);
    cudaGetSymbolAddress((void**)&qh,  g_qh);
    cudaGetSymbolAddress((void**)&kh,  g_kh);
    cudaGetSymbolAddress((void**)&vh,  g_vh);
    cudaGetSymbolAddress((void**)&x0h, g_x0h);
    cudaGetSymbolAddress((void**)&att, g_att);
    cudaGetSymbolAddress((void**)&x0f, g_x0f);

    const int GEMM_SMEM  = 65536;
    const int FLASH_SMEM = 174080;
    cudaFuncSetAttribute(gemm_h<0>, cudaFuncAttributeMaxDynamicSharedMemorySize, GEMM_SMEM);
    cudaFuncSetAttribute(gemm_h<3>, cudaFuncAttributeMaxDynamicSharedMemorySize, GEMM_SMEM);
    cudaFuncSetAttribute(flash_h,   cudaFuncAttributeMaxDynamicSharedMemorySize, FLASH_SMEM);

    const int NA = NROWS * DMODEL;     // 8M
    const int NW = DMODEL * DMODEL;    // 1M

    // conversions: Q/K (2-way batch), weights (4-way batch)
    ConvArgs cqk; cqk.s[0] = Q;  cqk.s[1] = K_; cqk.d[0] = Qh;  cqk.d[1] = Kh;
    cqk.s[2] = Q; cqk.s[3] = Q; cqk.d[2] = Qh; cqk.d[3] = Qh;   // unused slots
    conv_f2h<<<dim3(NA / 1024, 2), 256>>>(cqk, NA);
    ConvArgs cw;
    cw.s[0] = Wq; cw.s[1] = Wk; cw.s[2] = Wv; cw.s[3] = Wo;
    cw.d[0] = Wqh; cw.d[1] = Wkh; cw.d[2] = Wvh; cw.d[3] = Woh;
    conv_f2h<<<dim3(NW / 1024, 4), 256>>>(cw, NW);

    // fused projections: q/k/v in one launch
    GemmArgs gaP = {};
    gaP.A[0] = Qh; gaP.A[1] = Kh; gaP.A[2] = Kh;
    gaP.B[0] = Wqh; gaP.B[1] = Wkh; gaP.B[2] = Wvh;
    gaP.C[0] = qh; gaP.C[1] = kh; gaP.C[2] = vh;
    gaP.bias[0] = bq; gaP.bias[1] = bk; gaP.bias[2] = bv;
    dim3 blk(256);
    gemm_h<0><<<dim3(DMODEL / 128, NROWS / 128, 3), blk, GEMM_SMEM>>>(gaP);

    dim3 gf(NKEYS / 128, NBH);                   // (16, 32)
    flash_h<<<gf, blk, FLASH_SMEM>>>(qh, kh, vh, att);

    ln_kernel<true><<<NROWS, 256>>>(att, x0f, x0h, g0, b0);

    GemmArgs gaO = {};
    gaO.A[0] = x0h; gaO.B[0] = Woh; gaO.C[0] = att; gaO.bias[0] = bo;
    gaO.Res = x0f;
    gemm_h<3><<<dim3(DMODEL / 128, NROWS / 128, 1), blk, GEMM_SMEM>>>(gaO);

    ln_kernel<false><<<NROWS, 256>>>(att, out, nullptr, g1, b1);
}

// round 10
// speedup vs baseline: 1.0326x; 1.0326x over previous
#include <cuda_runtime.h>
#include <cuda_fp16.h>
#include <cstdint>

#define NROWS   8192
#define DMODEL  1024
#define NKEYS   2048
#define NBH     32

__device__ __half g_Qh [NROWS * DMODEL];
__device__ __half g_Kh [NROWS * DMODEL];
__device__ __half g_Wqh[DMODEL * DMODEL];
__device__ __half g_Wkh[DMODEL * DMODEL];
__device__ __half g_Wvh[DMODEL * DMODEL];
__device__ __half g_Woh[DMODEL * DMODEL];
__device__ __half g_qh [NROWS * DMODEL];
__device__ __half g_kh [NROWS * DMODEL];
__device__ __half g_vh [NROWS * DMODEL];
__device__ __half g_x0h[NROWS * DMODEL];
__device__ float  g_att[NROWS * DMODEL];
__device__ float  g_x0f[NROWS * DMODEL];

__device__ __forceinline__ uint32_t h2u(__half2 h) {
    uint32_t u;
    asm("mov.b32 %0, %1;" : "=r"(u) : "r"(*(uint32_t*)&h));
    return u;
}
__device__ __forceinline__ float ex2(float x) {
    float y;
    asm("ex2.approx.f32 %0, %1;" : "=f"(y) : "f"(x));
    return y;
}
__device__ __forceinline__ void ldsm4(uint32_t a[4], uint32_t addr) {
    asm volatile("ldmatrix.sync.aligned.m8n8.x4.shared.b16 {%0,%1,%2,%3}, [%4];"
                 : "=r"(a[0]), "=r"(a[1]), "=r"(a[2]), "=r"(a[3]) : "r"(addr));
}
__device__ __forceinline__ void ldsm4t(uint32_t a[4], uint32_t addr) {
    asm volatile("ldmatrix.sync.aligned.m8n8.x4.trans.shared.b16 {%0,%1,%2,%3}, [%4];"
                 : "=r"(a[0]), "=r"(a[1]), "=r"(a[2]), "=r"(a[3]) : "r"(addr));
}
__device__ __forceinline__ void mma_h(float* c, const uint32_t a[4], uint32_t b0, uint32_t b1) {
    asm volatile("mma.sync.aligned.m16n8k16.row.col.f32.f16.f16.f32 "
                 "{%0,%1,%2,%3}, {%4,%5,%6,%7}, {%8,%9}, {%0,%1,%2,%3};"
                 : "+f"(c[0]), "+f"(c[1]), "+f"(c[2]), "+f"(c[3])
                 : "r"(a[0]), "r"(a[1]), "r"(a[2]), "r"(a[3]), "r"(b0), "r"(b1));
}
__device__ __forceinline__ void cp16(uint32_t dst, const void* src) {
    asm volatile("cp.async.ca.shared.global [%0], [%1], 16;\n" :: "r"(dst), "l"(src));
}
#define CP_COMMIT() asm volatile("cp.async.commit_group;\n")
#define CP_WAIT1()  asm volatile("cp.async.wait_group 1;\n")
#define CP_WAIT2()  asm volatile("cp.async.wait_group 2;\n")

__device__ __forceinline__ float warpSum(float v) {
    #pragma unroll
    for (int o = 16; o; o >>= 1) v += __shfl_xor_sync(0xFFFFFFFFu, v, o);
    return v;
}
__device__ __forceinline__ float quadMax(float v) {
    v = fmaxf(v, __shfl_xor_sync(0xFFFFFFFFu, v, 1));
    v = fmaxf(v, __shfl_xor_sync(0xFFFFFFFFu, v, 2));
    return v;
}
__device__ __forceinline__ float quadSum(float v) {
    v += __shfl_xor_sync(0xFFFFFFFFu, v, 1);
    v += __shfl_xor_sync(0xFFFFFFFFu, v, 2);
    return v;
}

// ---------------- batched fp32 -> fp16 ----------------
struct ConvArgs { const float* s[4]; __half* d[4]; };

__global__ __launch_bounds__(256)
void conv_f2h(ConvArgs ca, int n)
{
    const float* s = ca.s[blockIdx.y];
    __half*      d = ca.d[blockIdx.y];
    int i = (blockIdx.x * 256 + threadIdx.x) * 4;
    if (i < n) {
        float4 v = *(const float4*)(s + i);
        __half2* o = (__half2*)(d + i);
        o[0] = __floats2half2_rn(v.x, v.y);
        o[1] = __floats2half2_rn(v.z, v.w);
    }
}

// ---------------------------------------------------------------------------
// fp16 GEMM C = epi(A @ B^T), batched over blockIdx.z (pointer arrays).
// ---------------------------------------------------------------------------
struct GemmArgs {
    const __half* A[3];
    const __half* B[3];
    void*         C[3];
    const float*  bias[3];
    const float*  Res;
};

template<int EPI>
__global__ __launch_bounds__(256, 2)
void gemm_h(GemmArgs ga)
{
    extern __shared__ char smc[];
    const uint32_t smA = (uint32_t)__cvta_generic_to_shared(smc);
    const uint32_t smB = smA + 32768;

    const int z = blockIdx.z;
    const __half* __restrict__ A = ga.A[z];
    const __half* __restrict__ B = ga.B[z];
    void* Cv = ga.C[z];
    const float* __restrict__ bias = ga.bias[z];
    const float* __restrict__ Res = ga.Res;

    const int m0 = blockIdx.y * 128, n0 = blockIdx.x * 128;
    const int tid = threadIdx.x, warp = tid >> 5, lane = tid & 31;
    const int wm = (warp >> 2) * 64, wn = (warp & 3) * 32;
    const int g = lane >> 2, tg = lane & 3;
    const uint32_t l7 = lane & 7, lb3 = (lane >> 3) & 1, lb4 = (uint32_t)lane >> 4;

    float acc[4][4][4];
    #pragma unroll
    for (int i = 0; i < 4; i++)
        #pragma unroll
        for (int j = 0; j < 4; j++)
            #pragma unroll
            for (int e = 0; e < 4; e++) acc[i][j][e] = 0.f;

    auto stage = [&](int s, int k0) {
        #pragma unroll
        for (int i = 0; i < 4; i++) {
            int idx = tid + i * 256;
            uint32_t row = idx >> 3, c = idx & 7;
            uint32_t d = s * 16384 + row * 128 + ((c ^ (row & 7)) * 16);
            cp16(smA + d, A + (long)(m0 + row) * DMODEL + k0 + c * 8);
            cp16(smB + d, B + (long)(n0 + row) * DMODEL + k0 + c * 8);
        }
    };
    stage(0, 0);  CP_COMMIT();
    stage(1, 64); CP_COMMIT();

    for (int kt = 0; kt < 16; kt++) {
        CP_WAIT1();
        __syncthreads();
        const uint32_t sa = smA + (kt & 1) * 16384;
        const uint32_t sb = smB + (kt & 1) * 16384;
        #pragma unroll
        for (int ks = 0; ks < 4; ks++) {
            uint32_t af[4][4], bf[2][4];
            #pragma unroll
            for (int mi = 0; mi < 4; mi++) {
                uint32_t row = wm + mi * 16 + lb3 * 8 + l7;
                uint32_t cc  = ks * 2 + lb4;
                ldsm4(af[mi], sa + row * 128 + ((cc ^ (row & 7)) * 16));
            }
            #pragma unroll
            for (int nj = 0; nj < 2; nj++) {
                uint32_t row = wn + nj * 16 + lb4 * 8 + l7;
                uint32_t cc  = ks * 2 + lb3;
                ldsm4(bf[nj], sb + row * 128 + ((cc ^ (row & 7)) * 16));
            }
            #pragma unroll
            for (int mi = 0; mi < 4; mi++)
                #pragma unroll
                for (int nf = 0; nf < 4; nf++)
                    mma_h(acc[mi][nf], af[mi], bf[nf >> 1][(nf & 1) * 2],
                          bf[nf >> 1][(nf & 1) * 2 + 1]);
        }
        __syncthreads();
        if (kt < 14) stage(kt & 1, (kt + 2) * 64);
        CP_COMMIT();
    }

    #pragma unroll
    for (int mi = 0; mi < 4; mi++) {
        #pragma unroll
        for (int nf = 0; nf < 4; nf++) {
            int r = m0 + wm + mi * 16 + g;
            int c = n0 + wn + nf * 8 + 2 * tg;
            float b0 = bias[c], b1 = bias[c + 1];
            if (EPI == 0) {
                __half* C = (__half*)Cv;
                *(__half2*)(C + (long)r * DMODEL + c) =
                    __floats2half2_rn(acc[mi][nf][0] + b0, acc[mi][nf][1] + b1);
                *(__half2*)(C + (long)(r + 8) * DMODEL + c) =
                    __floats2half2_rn(acc[mi][nf][2] + b0, acc[mi][nf][3] + b1);
            } else {
                float* C = (float*)Cv;
                float2 v0, v1;
                v0.x = fmaxf(acc[mi][nf][0] + b0, 0.f) + Res[(long)r * DMODEL + c];
                v0.y = fmaxf(acc[mi][nf][1] + b1, 0.f) + Res[(long)r * DMODEL + c + 1];
                v1.x = fmaxf(acc[mi][nf][2] + b0, 0.f) + Res[(long)(r + 8) * DMODEL + c];
                v1.y = fmaxf(acc[mi][nf][3] + b1, 0.f) + Res[(long)(r + 8) * DMODEL + c + 1];
                *(float2*)(C + (long)r * DMODEL + c) = v0;
                *(float2*)(C + (long)(r + 8) * DMODEL + c) = v1;
            }
        }
    }
}

// ---------------------------------------------------------------------------
// fp16 flash: CTA = one (b,h), 128 q-rows; 32 tiles of 64 keys.
// 4-slot K/V ring, 3 tiles in flight, prefetch issued BEFORE compute.
// Q fragments hoisted to registers; P stays in registers; ex2-domain softmax.
// smem: Q [0,34816) | K 4x17408 [34816,104448) | V 4x17408 [104448,174080)
// ---------------------------------------------------------------------------
__global__ __launch_bounds__(256, 1)
void flash_h(const __half* __restrict__ qb, const __half* __restrict__ kb,
             const __half* __restrict__ vb, float* __restrict__ att)
{
    extern __shared__ char smc[];
    const uint32_t smQ = (uint32_t)__cvta_generic_to_shared(smc);
    const uint32_t smK = smQ + 34816;
    const uint32_t smV = smQ + 104448;

    const int bh = blockIdx.y, zb = bh >> 3, zh = bh & 7;
    const long base = (long)zb * (NKEYS * DMODEL) + zh * 128;
    const __half* qp = qb + base + (long)blockIdx.x * 128 * DMODEL;
    const __half* kp = kb + base;
    const __half* vp = vb + base;
    float*        op = att + base + (long)blockIdx.x * 128 * DMODEL;

    const int tid = threadIdx.x, warp = tid >> 5, lane = tid & 31;
    const int g = lane >> 2, tg = lane & 3;
    const int wr = warp * 16;
    const uint32_t l7 = lane & 7, lb3 = (lane >> 3) & 1, lb4 = (uint32_t)lane >> 4;
    // log2(e)/sqrt(128): softmax computed in base-2 domain (exact identity)
    const float isq2 = 0.088388347648318447f * 1.44269504088896341f;

    // stage Q (commit group 0, together with KV tile 0)
    #pragma unroll
    for (int i = 0; i < 8; i++) {
        int idx = tid + i * 256;
        uint32_t r = idx >> 4, c = idx & 15;
        cp16(smQ + r * 272 + c * 16, qp + (long)r * DMODEL + c * 8);
    }
    auto stage = [&](int s, int jt) {
        #pragma unroll
        for (int i = 0; i < 4; i++) {
            int idx = tid + i * 256;
            uint32_t r = idx >> 4, c = idx & 15;
            const long go = (long)(jt * 64 + r) * DMODEL + c * 8;
            uint32_t d = s * 17408 + r * 272 + c * 16;
            cp16(smK + d, kp + go);
            cp16(smV + d, vp + go);
        }
    };
    stage(0, 0); CP_COMMIT();
    stage(1, 1); CP_COMMIT();
    stage(2, 2); CP_COMMIT();

    // group 0 (Q + tile 0) complete -> hoist Q fragments into registers
    CP_WAIT2();
    __syncthreads();
    uint32_t qa[8][4];
    {
        uint32_t row = wr + lb3 * 8 + l7;
        #pragma unroll
        for (int ks = 0; ks < 8; ks++)
            ldsm4(qa[ks], smQ + row * 272 + (ks * 2 + lb4) * 16);
    }

    float o[16][4];
    #pragma unroll
    for (int f = 0; f < 16; f++)
        #pragma unroll
        for (int e = 0; e < 4; e++) o[f][e] = 0.f;
    float m0 = -1e30f, m1 = -1e30f, l0 = 0.f, l1 = 0.f;

    for (int j = 0; j < 32; j++) {
        if (j) { CP_WAIT2(); __syncthreads(); }
        const uint32_t sk = smK + (j & 3) * 17408;
        const uint32_t sv = smV + (j & 3) * 17408;

        // prefetch tile j+3 into slot (j+3)&3 (readers of that slot finished
        // in iteration j-1; the syncthreads above proves it)
        if (j + 3 < 32) stage((j + 3) & 3, j + 3);
        CP_COMMIT();

        // ---- S = Q K^T ----
        float s[8][4];
        #pragma unroll
        for (int t = 0; t < 8; t++)
            #pragma unroll
            for (int e = 0; e < 4; e++) s[t][e] = 0.f;
        #pragma unroll
        for (int ks = 0; ks < 8; ks++) {
            #pragma unroll
            for (int nt = 0; nt < 4; nt++) {
                uint32_t kf[4];
                uint32_t row = nt * 16 + lb4 * 8 + l7;
                ldsm4(kf, sk + row * 272 + (ks * 2 + lb3) * 16);
                mma_h(s[nt * 2],     qa[ks], kf[0], kf[1]);
                mma_h(s[nt * 2 + 1], qa[ks], kf[2], kf[3]);
            }
        }

        // ---- online softmax in log2 domain ----
        float tm0 = -1e30f, tm1 = -1e30f;
        #pragma unroll
        for (int t = 0; t < 8; t++) {
            s[t][0] *= isq2; s[t][1] *= isq2; s[t][2] *= isq2; s[t][3] *= isq2;
            tm0 = fmaxf(tm0, fmaxf(s[t][0], s[t][1]));
            tm1 = fmaxf(tm1, fmaxf(s[t][2], s[t][3]));
        }
        tm0 = quadMax(tm0); tm1 = quadMax(tm1);
        float mn0 = fmaxf(m0, tm0), mn1 = fmaxf(m1, tm1);
        float sc0 = ex2(m0 - mn0), sc1 = ex2(m1 - mn1);
        m0 = mn0; m1 = mn1;
        float ls0 = 0.f, ls1 = 0.f;
        uint32_t ah[8][2];
        #pragma unroll
        for (int t = 0; t < 8; t++) {
            s[t][0] = ex2(s[t][0] - mn0);
            s[t][1] = ex2(s[t][1] - mn0);
            s[t][2] = ex2(s[t][2] - mn1);
            s[t][3] = ex2(s[t][3] - mn1);
            ls0 += s[t][0] + s[t][1];
            ls1 += s[t][2] + s[t][3];
            ah[t][0] = h2u(__floats2half2_rn(s[t][0], s[t][1]));
            ah[t][1] = h2u(__floats2half2_rn(s[t][2], s[t][3]));
        }
        l0 = l0 * sc0 + ls0;
        l1 = l1 * sc1 + ls1;
        #pragma unroll
        for (int f = 0; f < 16; f++) {
            o[f][0] *= sc0; o[f][1] *= sc0;
            o[f][2] *= sc1; o[f][3] *= sc1;
        }

        // ---- O += P V ----
        #pragma unroll
        for (int kv = 0; kv < 4; kv++) {
            uint32_t pa[4] = { ah[2*kv][0], ah[2*kv][1], ah[2*kv+1][0], ah[2*kv+1][1] };
            #pragma unroll
            for (int nt2 = 0; nt2 < 8; nt2++) {
                uint32_t vf[4];
                uint32_t row = kv * 16 + lb3 * 8 + l7;
                ldsm4t(vf, sv + row * 272 + (nt2 * 2 + lb4) * 16);
                mma_h(o[nt2 * 2],     pa, vf[0], vf[1]);
                mma_h(o[nt2 * 2 + 1], pa, vf[2], vf[3]);
            }
        }
    }

    // ---- epilogue: out = q + O / l ----
    l0 = quadSum(l0); l1 = quadSum(l1);
    const float i0 = 1.f / l0, i1 = 1.f / l1;
    const int r0 = wr + g, r1 = wr + g + 8;
    #pragma unroll
    for (int nf = 0; nf < 16; nf++) {
        int c = nf * 8 + 2 * tg;
        float2 q0 = __half22float2(*(const __half2*)(qp + (long)r0 * DMODEL + c));
        float2 q1 = __half22float2(*(const __half2*)(qp + (long)r1 * DMODEL + c));
        *(float2*)(op + (long)r0 * DMODEL + c) =
            make_float2(q0.x + o[nf][0] * i0, q0.y + o[nf][1] * i0);
        *(float2*)(op + (long)r1 * DMODEL + c) =
            make_float2(q1.x + o[nf][2] * i1, q1.y + o[nf][3] * i1);
    }
}

// ---------------------------------------------------------------------------
// LayerNorm (rows of 1024). WH: also emit half copy.
// ---------------------------------------------------------------------------
template<bool WH>
__global__ __launch_bounds__(256)
void ln_kernel(const float* __restrict__ X, float* __restrict__ Y,
               __half* __restrict__ Yh,
               const float* __restrict__ gam, const float* __restrict__ bet)
{
    const float* x = X + (size_t)blockIdx.x * DMODEL;
    float*       y = Y + (size_t)blockIdx.x * DMODEL;
    __half*      yh = WH ? (Yh + (size_t)blockIdx.x * DMODEL) : nullptr;
    const int tid = threadIdx.x;
    float v[4];
    float s = 0.f, sq = 0.f;
    #pragma unroll
    for (int i = 0; i < 4; i++) {
        v[i] = x[i * 256 + tid];
        s  += v[i];
        sq += v[i] * v[i];
    }
    s  = warpSum(s);
    sq = warpSum(sq);
    __shared__ float a1[8], a2[8];
    if ((tid & 31) == 0) { a1[tid >> 5] = s; a2[tid >> 5] = sq; }
    __syncthreads();
    float S1 = ((a1[0] + a1[1]) + (a1[2] + a1[3])) + ((a1[4] + a1[5]) + (a1[6] + a1[7]));
    float S2 = ((a2[0] + a2[1]) + (a2[2] + a2[3])) + ((a2[4] + a2[5]) + (a2[6] + a2[7]));
    float mu  = S1 * (1.f / DMODEL);
    float var = S2 * (1.f / DMODEL) - mu * mu;
    float rs  = rsqrtf(var + 1e-5f);
    #pragma unroll
    for (int i = 0; i < 4; i++) {
        int c = i * 256 + tid;
        float r = (v[i] - mu) * rs * gam[c] + bet[c];
        y[c] = r;
        if (WH) yh[c] = __float2half_rn(r);
    }
}

// ---------------------------------------------------------------------------
extern "C" void kernel_launch(void* const* d_in, const int* in_sizes, int n_in,
                              void* d_out, int out_size)
{
    (void)in_sizes; (void)n_in; (void)out_size;
    const float* Q  = (const float*)d_in[0];
    const float* K_ = (const float*)d_in[1];
    const float* Wq = (const float*)d_in[2];
    const float* bq = (const float*)d_in[3];
    const float* Wk = (const float*)d_in[4];
    const float* bk = (const float*)d_in[5];
    const float* Wv = (const float*)d_in[6];
    const float* bv = (const float*)d_in[7];
    const float* Wo = (const float*)d_in[8];
    const float* bo = (const float*)d_in[9];
    const float* g0 = (const float*)d_in[10];
    const float* b0 = (const float*)d_in[11];
    const float* g1 = (const float*)d_in[12];
    const float* b1 = (const float*)d_in[13];
    float* out = (float*)d_out;

    __half *Qh, *Kh, *Wqh, *Wkh, *Wvh, *Woh, *qh, *kh, *vh, *x0h;
    float *att, *x0f;
    cudaGetSymbolAddress((void**)&Qh,  g_Qh);
    cudaGetSymbolAddress((void**)&Kh,  g_Kh);
    cudaGetSymbolAddress((void**)&Wqh, g_Wqh);
    cudaGetSymbolAddress((void**)&Wkh, g_Wkh);
    cudaGetSymbolAddress((void**)&Wvh, g_Wvh);
    cudaGetSymbolAddress((void**)&Woh, g_Woh);
    cudaGetSymbolAddress((void**)&qh,  g_qh);
    cudaGetSymbolAddress((void**)&kh,  g_kh);
    cudaGetSymbolAddress((void**)&vh,  g_vh);
    cudaGetSymbolAddress((void**)&x0h, g_x0h);
    cudaGetSymbolAddress((void**)&att, g_att);
    cudaGetSymbolAddress((void**)&x0f, g_x0f);

    const int GEMM_SMEM  = 65536;
    const int FLASH_SMEM = 174080;
    cudaFuncSetAttribute(gemm_h<0>, cudaFuncAttributeMaxDynamicSharedMemorySize, GEMM_SMEM);
    cudaFuncSetAttribute(gemm_h<3>, cudaFuncAttributeMaxDynamicSharedMemorySize, GEMM_SMEM);
    cudaFuncSetAttribute(flash_h,   cudaFuncAttributeMaxDynamicSharedMemorySize, FLASH_SMEM);

    const int NA = NROWS * DMODEL;     // 8M
    const int NW = DMODEL * DMODEL;    // 1M

    ConvArgs cqk; cqk.s[0] = Q;  cqk.s[1] = K_; cqk.d[0] = Qh;  cqk.d[1] = Kh;
    cqk.s[2] = Q; cqk.s[3] = Q; cqk.d[2] = Qh; cqk.d[3] = Qh;
    conv_f2h<<<dim3(NA / 1024, 2), 256>>>(cqk, NA);
    ConvArgs cw;
    cw.s[0] = Wq; cw.s[1] = Wk; cw.s[2] = Wv; cw.s[3] = Wo;
    cw.d[0] = Wqh; cw.d[1] = Wkh; cw.d[2] = Wvh; cw.d[3] = Woh;
    conv_f2h<<<dim3(NW / 1024, 4), 256>>>(cw, NW);

    GemmArgs gaP = {};
    gaP.A[0] = Qh; gaP.A[1] = Kh; gaP.A[2] = Kh;
    gaP.B[0] = Wqh; gaP.B[1] = Wkh; gaP.B[2] = Wvh;
    gaP.C[0] = qh; gaP.C[1] = kh; gaP.C[2] = vh;
    gaP.bias[0] = bq; gaP.bias[1] = bk; gaP.bias[2] = bv;
    dim3 blk(256);
    gemm_h<0><<<dim3(DMODEL / 128, NROWS / 128, 3), blk, GEMM_SMEM>>>(gaP);

    dim3 gf(NKEYS / 128, NBH);                   // (16, 32)
    flash_h<<<gf, blk, FLASH_SMEM>>>(qh, kh, vh, att);

    ln_kernel<true><<<NROWS, 256>>>(att, x0f, x0h, g0, b0);

    GemmArgs gaO = {};
    gaO.A[0] = x0h; gaO.B[0] = Woh; gaO.C[0] = att; gaO.bias[0] = bo;
    gaO.Res = x0f;
    gemm_h<3><<<dim3(DMODEL / 128, NROWS / 128, 1), blk, GEMM_SMEM>>>(gaO);

    ln_kernel<false><<<NROWS, 256>>>(att, out, nullptr, g1, b1);
}

// round 11
// speedup vs baseline: 1.0566x; 1.0232x over previous
#include <cuda_runtime.h>
#include <cuda_fp16.h>
#include <cstdint>

#define NROWS   8192
#define DMODEL  1024
#define NKEYS   2048
#define NBH     32

__device__ __half g_Qh [NROWS * DMODEL];
__device__ __half g_Kh [NROWS * DMODEL];
__device__ __half g_Wqh[DMODEL * DMODEL];
__device__ __half g_Wkh[DMODEL * DMODEL];
__device__ __half g_Wvh[DMODEL * DMODEL];
__device__ __half g_Woh[DMODEL * DMODEL];
__device__ __half g_qh [NROWS * DMODEL];
__device__ __half g_kh [NROWS * DMODEL];
__device__ __half g_vh [NROWS * DMODEL];
__device__ __half g_x0h[NROWS * DMODEL];
__device__ float  g_att[NROWS * DMODEL];
__device__ float  g_x0f[NROWS * DMODEL];

__device__ __forceinline__ uint32_t h2u(__half2 h) {
    uint32_t u;
    asm("mov.b32 %0, %1;" : "=r"(u) : "r"(*(uint32_t*)&h));
    return u;
}
__device__ __forceinline__ float ex2(float x) {
    float y;
    asm("ex2.approx.f32 %0, %1;" : "=f"(y) : "f"(x));
    return y;
}
__device__ __forceinline__ void ldsm4(uint32_t a[4], uint32_t addr) {
    asm volatile("ldmatrix.sync.aligned.m8n8.x4.shared.b16 {%0,%1,%2,%3}, [%4];"
                 : "=r"(a[0]), "=r"(a[1]), "=r"(a[2]), "=r"(a[3]) : "r"(addr));
}
__device__ __forceinline__ void ldsm4t(uint32_t a[4], uint32_t addr) {
    asm volatile("ldmatrix.sync.aligned.m8n8.x4.trans.shared.b16 {%0,%1,%2,%3}, [%4];"
                 : "=r"(a[0]), "=r"(a[1]), "=r"(a[2]), "=r"(a[3]) : "r"(addr));
}
__device__ __forceinline__ void mma_h(float* c, const uint32_t a[4], uint32_t b0, uint32_t b1) {
    asm volatile("mma.sync.aligned.m16n8k16.row.col.f32.f16.f16.f32 "
                 "{%0,%1,%2,%3}, {%4,%5,%6,%7}, {%8,%9}, {%0,%1,%2,%3};"
                 : "+f"(c[0]), "+f"(c[1]), "+f"(c[2]), "+f"(c[3])
                 : "r"(a[0]), "r"(a[1]), "r"(a[2]), "r"(a[3]), "r"(b0), "r"(b1));
}
__device__ __forceinline__ void cp16(uint32_t dst, const void* src) {
    asm volatile("cp.async.ca.shared.global [%0], [%1], 16;\n" :: "r"(dst), "l"(src));
}
#define CP_COMMIT() asm volatile("cp.async.commit_group;\n")
#define CP_WAIT1()  asm volatile("cp.async.wait_group 1;\n")
#define CP_WAIT2()  asm volatile("cp.async.wait_group 2;\n")

__device__ __forceinline__ float warpSum(float v) {
    #pragma unroll
    for (int o = 16; o; o >>= 1) v += __shfl_xor_sync(0xFFFFFFFFu, v, o);
    return v;
}
__device__ __forceinline__ float quadMax(float v) {
    v = fmaxf(v, __shfl_xor_sync(0xFFFFFFFFu, v, 1));
    v = fmaxf(v, __shfl_xor_sync(0xFFFFFFFFu, v, 2));
    return v;
}
__device__ __forceinline__ float quadSum(float v) {
    v += __shfl_xor_sync(0xFFFFFFFFu, v, 1);
    v += __shfl_xor_sync(0xFFFFFFFFu, v, 2);
    return v;
}

// ---------------- batched fp32 -> fp16 ----------------
struct ConvArgs { const float* s[4]; __half* d[4]; };

__global__ __launch_bounds__(256)
void conv_f2h(ConvArgs ca, int n)
{
    const float* s = ca.s[blockIdx.y];
    __half*      d = ca.d[blockIdx.y];
    int i = (blockIdx.x * 256 + threadIdx.x) * 4;
    if (i < n) {
        float4 v = *(const float4*)(s + i);
        __half2* o = (__half2*)(d + i);
        o[0] = __floats2half2_rn(v.x, v.y);
        o[1] = __floats2half2_rn(v.z, v.w);
    }
}

// ---------------------------------------------------------------------------
// fp16 GEMM C = epi(A @ B^T), batched over blockIdx.z (pointer arrays).
// (unchanged from round 10)
// ---------------------------------------------------------------------------
struct GemmArgs {
    const __half* A[3];
    const __half* B[3];
    void*         C[3];
    const float*  bias[3];
    const float*  Res;
};

template<int EPI>
__global__ __launch_bounds__(256, 2)
void gemm_h(GemmArgs ga)
{
    extern __shared__ char smc[];
    const uint32_t smA = (uint32_t)__cvta_generic_to_shared(smc);
    const uint32_t smB = smA + 32768;

    const int z = blockIdx.z;
    const __half* __restrict__ A = ga.A[z];
    const __half* __restrict__ B = ga.B[z];
    void* Cv = ga.C[z];
    const float* __restrict__ bias = ga.bias[z];
    const float* __restrict__ Res = ga.Res;

    const int m0 = blockIdx.y * 128, n0 = blockIdx.x * 128;
    const int tid = threadIdx.x, warp = tid >> 5, lane = tid & 31;
    const int wm = (warp >> 2) * 64, wn = (warp & 3) * 32;
    const int g = lane >> 2, tg = lane & 3;
    const uint32_t l7 = lane & 7, lb3 = (lane >> 3) & 1, lb4 = (uint32_t)lane >> 4;

    float acc[4][4][4];
    #pragma unroll
    for (int i = 0; i < 4; i++)
        #pragma unroll
        for (int j = 0; j < 4; j++)
            #pragma unroll
            for (int e = 0; e < 4; e++) acc[i][j][e] = 0.f;

    auto stage = [&](int s, int k0) {
        #pragma unroll
        for (int i = 0; i < 4; i++) {
            int idx = tid + i * 256;
            uint32_t row = idx >> 3, c = idx & 7;
            uint32_t d = s * 16384 + row * 128 + ((c ^ (row & 7)) * 16);
            cp16(smA + d, A + (long)(m0 + row) * DMODEL + k0 + c * 8);
            cp16(smB + d, B + (long)(n0 + row) * DMODEL + k0 + c * 8);
        }
    };
    stage(0, 0);  CP_COMMIT();
    stage(1, 64); CP_COMMIT();

    for (int kt = 0; kt < 16; kt++) {
        CP_WAIT1();
        __syncthreads();
        const uint32_t sa = smA + (kt & 1) * 16384;
        const uint32_t sb = smB + (kt & 1) * 16384;
        #pragma unroll
        for (int ks = 0; ks < 4; ks++) {
            uint32_t af[4][4], bf[2][4];
            #pragma unroll
            for (int mi = 0; mi < 4; mi++) {
                uint32_t row = wm + mi * 16 + lb3 * 8 + l7;
                uint32_t cc  = ks * 2 + lb4;
                ldsm4(af[mi], sa + row * 128 + ((cc ^ (row & 7)) * 16));
            }
            #pragma unroll
            for (int nj = 0; nj < 2; nj++) {
                uint32_t row = wn + nj * 16 + lb4 * 8 + l7;
                uint32_t cc  = ks * 2 + lb3;
                ldsm4(bf[nj], sb + row * 128 + ((cc ^ (row & 7)) * 16));
            }
            #pragma unroll
            for (int mi = 0; mi < 4; mi++)
                #pragma unroll
                for (int nf = 0; nf < 4; nf++)
                    mma_h(acc[mi][nf], af[mi], bf[nf >> 1][(nf & 1) * 2],
                          bf[nf >> 1][(nf & 1) * 2 + 1]);
        }
        __syncthreads();
        if (kt < 14) stage(kt & 1, (kt + 2) * 64);
        CP_COMMIT();
    }

    #pragma unroll
    for (int mi = 0; mi < 4; mi++) {
        #pragma unroll
        for (int nf = 0; nf < 4; nf++) {
            int r = m0 + wm + mi * 16 + g;
            int c = n0 + wn + nf * 8 + 2 * tg;
            float b0 = bias[c], b1 = bias[c + 1];
            if (EPI == 0) {
                __half* C = (__half*)Cv;
                *(__half2*)(C + (long)r * DMODEL + c) =
                    __floats2half2_rn(acc[mi][nf][0] + b0, acc[mi][nf][1] + b1);
                *(__half2*)(C + (long)(r + 8) * DMODEL + c) =
                    __floats2half2_rn(acc[mi][nf][2] + b0, acc[mi][nf][3] + b1);
            } else {
                float* C = (float*)Cv;
                float2 v0, v1;
                v0.x = fmaxf(acc[mi][nf][0] + b0, 0.f) + Res[(long)r * DMODEL + c];
                v0.y = fmaxf(acc[mi][nf][1] + b1, 0.f) + Res[(long)r * DMODEL + c + 1];
                v1.x = fmaxf(acc[mi][nf][2] + b0, 0.f) + Res[(long)(r + 8) * DMODEL + c];
                v1.y = fmaxf(acc[mi][nf][3] + b1, 0.f) + Res[(long)(r + 8) * DMODEL + c + 1];
                *(float2*)(C + (long)r * DMODEL + c) = v0;
                *(float2*)(C + (long)(r + 8) * DMODEL + c) = v1;
            }
        }
    }
}

// ---------------------------------------------------------------------------
// fp16 flash, BM=256: CTA = one (b,h) x 256 q-rows; warp owns 32 rows.
// K/V fragments amortized over 2 row-tiles -> crossbar/FLOP x0.625.
// 4-slot K/V ring, prefetch distance 3, issued before compute.
// smem: Q 256x272 [0,69632) | K 4x17408 [69632,139264) | V 4x17408 [139264,208896)
// ---------------------------------------------------------------------------
__global__ __launch_bounds__(256, 1)
void flash_h(const __half* __restrict__ qb, const __half* __restrict__ kb,
             const __half* __restrict__ vb, float* __restrict__ att)
{
    extern __shared__ char smc[];
    const uint32_t smQ = (uint32_t)__cvta_generic_to_shared(smc);
    const uint32_t smK = smQ + 69632;
    const uint32_t smV = smQ + 139264;

    const int bh = blockIdx.y, zb = bh >> 3, zh = bh & 7;
    const long base = (long)zb * (NKEYS * DMODEL) + zh * 128;
    const __half* qp = qb + base + (long)blockIdx.x * 256 * DMODEL;
    const __half* kp = kb + base;
    const __half* vp = vb + base;
    float*        op = att + base + (long)blockIdx.x * 256 * DMODEL;

    const int tid = threadIdx.x, warp = tid >> 5, lane = tid & 31;
    const int g = lane >> 2, tg = lane & 3;
    const int wr = warp * 32;
    const uint32_t l7 = lane & 7, lb3 = (lane >> 3) & 1, lb4 = (uint32_t)lane >> 4;
    const float isq2 = 0.088388347648318447f * 1.44269504088896341f;  // log2e/sqrt(d)

    // stage Q: 256 rows x 16 chunks (commit group 0, with KV tile 0)
    #pragma unroll
    for (int i = 0; i < 16; i++) {
        int idx = tid + i * 256;
        uint32_t r = idx >> 4, c = idx & 15;
        cp16(smQ + r * 272 + c * 16, qp + (long)r * DMODEL + c * 8);
    }
    auto stage = [&](int s, int jt) {
        #pragma unroll
        for (int i = 0; i < 4; i++) {
            int idx = tid + i * 256;
            uint32_t r = idx >> 4, c = idx & 15;
            const long go = (long)(jt * 64 + r) * DMODEL + c * 8;
            uint32_t d = s * 17408 + r * 272 + c * 16;
            cp16(smK + d, kp + go);
            cp16(smV + d, vp + go);
        }
    };
    stage(0, 0); CP_COMMIT();
    stage(1, 1); CP_COMMIT();
    stage(2, 2); CP_COMMIT();

    CP_WAIT2();
    __syncthreads();

    float o0[16][4], o1[16][4];
    #pragma unroll
    for (int f = 0; f < 16; f++)
        #pragma unroll
        for (int e = 0; e < 4; e++) { o0[f][e] = 0.f; o1[f][e] = 0.f; }
    float m00 = -1e30f, m01 = -1e30f, l00 = 0.f, l01 = 0.f;   // rt0 rows g, g+8
    float m10 = -1e30f, m11 = -1e30f, l10 = 0.f, l11 = 0.f;   // rt1

    const uint32_t qrow0 = wr + lb3 * 8 + l7;
    const uint32_t qrow1 = qrow0 + 16;

    // softmax+rescale for one row-tile (s consumed into ah)
    auto softmax = [&](float (&s)[8][4], float& m0, float& m1, float& l0, float& l1,
                       uint32_t (&ah)[8][2], float (&o)[16][4]) {
        float tm0 = -1e30f, tm1 = -1e30f;
        #pragma unroll
        for (int t = 0; t < 8; t++) {
            s[t][0] *= isq2; s[t][1] *= isq2; s[t][2] *= isq2; s[t][3] *= isq2;
            tm0 = fmaxf(tm0, fmaxf(s[t][0], s[t][1]));
            tm1 = fmaxf(tm1, fmaxf(s[t][2], s[t][3]));
        }
        tm0 = quadMax(tm0); tm1 = quadMax(tm1);
        float mn0 = fmaxf(m0, tm0), mn1 = fmaxf(m1, tm1);
        float sc0 = ex2(m0 - mn0), sc1 = ex2(m1 - mn1);
        m0 = mn0; m1 = mn1;
        float ls0 = 0.f, ls1 = 0.f;
        #pragma unroll
        for (int t = 0; t < 8; t++) {
            float e0 = ex2(s[t][0] - mn0);
            float e1 = ex2(s[t][1] - mn0);
            float e2 = ex2(s[t][2] - mn1);
            float e3 = ex2(s[t][3] - mn1);
            ls0 += e0 + e1;
            ls1 += e2 + e3;
            ah[t][0] = h2u(__floats2half2_rn(e0, e1));
            ah[t][1] = h2u(__floats2half2_rn(e2, e3));
        }
        l0 = l0 * sc0 + ls0;
        l1 = l1 * sc1 + ls1;
        #pragma unroll
        for (int f = 0; f < 16; f++) {
            o[f][0] *= sc0; o[f][1] *= sc0;
            o[f][2] *= sc1; o[f][3] *= sc1;
        }
    };

    for (int j = 0; j < 32; j++) {
        if (j) { CP_WAIT2(); __syncthreads(); }
        const uint32_t sk = smK + (j & 3) * 17408;
        const uint32_t sv = smV + (j & 3) * 17408;

        if (j + 3 < 32) stage((j + 3) & 3, j + 3);
        CP_COMMIT();

        // ---- S = Q K^T for both row-tiles; K fragment loaded once ----
        float s0[8][4], s1[8][4];
        #pragma unroll
        for (int t = 0; t < 8; t++)
            #pragma unroll
            for (int e = 0; e < 4; e++) { s0[t][e] = 0.f; s1[t][e] = 0.f; }
        #pragma unroll
        for (int ks = 0; ks < 8; ks++) {
            uint32_t qa0[4], qa1[4];
            ldsm4(qa0, smQ + qrow0 * 272 + (ks * 2 + lb4) * 16);
            ldsm4(qa1, smQ + qrow1 * 272 + (ks * 2 + lb4) * 16);
            #pragma unroll
            for (int nt = 0; nt < 4; nt++) {
                uint32_t kf[4];
                uint32_t row = nt * 16 + lb4 * 8 + l7;
                ldsm4(kf, sk + row * 272 + (ks * 2 + lb3) * 16);
                mma_h(s0[nt * 2],     qa0, kf[0], kf[1]);
                mma_h(s0[nt * 2 + 1], qa0, kf[2], kf[3]);
                mma_h(s1[nt * 2],     qa1, kf[0], kf[1]);
                mma_h(s1[nt * 2 + 1], qa1, kf[2], kf[3]);
            }
        }

        uint32_t ah0[8][2], ah1[8][2];
        softmax(s0, m00, m01, l00, l01, ah0, o0);
        softmax(s1, m10, m11, l10, l11, ah1, o1);

        // ---- O += P V for both row-tiles; V fragment loaded once ----
        #pragma unroll
        for (int kv = 0; kv < 4; kv++) {
            uint32_t pa0[4] = { ah0[2*kv][0], ah0[2*kv][1], ah0[2*kv+1][0], ah0[2*kv+1][1] };
            uint32_t pa1[4] = { ah1[2*kv][0], ah1[2*kv][1], ah1[2*kv+1][0], ah1[2*kv+1][1] };
            uint32_t vrow = kv * 16 + lb3 * 8 + l7;
            #pragma unroll
            for (int nt2 = 0; nt2 < 8; nt2++) {
                uint32_t vf[4];
                ldsm4t(vf, sv + vrow * 272 + (nt2 * 2 + lb4) * 16);
                mma_h(o0[nt2 * 2],     pa0, vf[0], vf[1]);
                mma_h(o0[nt2 * 2 + 1], pa0, vf[2], vf[3]);
                mma_h(o1[nt2 * 2],     pa1, vf[0], vf[1]);
                mma_h(o1[nt2 * 2 + 1], pa1, vf[2], vf[3]);
            }
        }
    }

    // ---- epilogue: out = q + O / l, both row-tiles ----
    {
        float la = quadSum(l00), lb = quadSum(l01);
        float i0 = 1.f / la, i1 = 1.f / lb;
        int r0 = wr + g, r1 = wr + g + 8;
        #pragma unroll
        for (int nf = 0; nf < 16; nf++) {
            int c = nf * 8 + 2 * tg;
            float2 q0 = __half22float2(*(const __half2*)(qp + (long)r0 * DMODEL + c));
            float2 q1 = __half22float2(*(const __half2*)(qp + (long)r1 * DMODEL + c));
            *(float2*)(op + (long)r0 * DMODEL + c) =
                make_float2(q0.x + o0[nf][0] * i0, q0.y + o0[nf][1] * i0);
            *(float2*)(op + (long)r1 * DMODEL + c) =
                make_float2(q1.x + o0[nf][2] * i1, q1.y + o0[nf][3] * i1);
        }
    }
    {
        float la = quadSum(l10), lb = quadSum(l11);
        float i0 = 1.f / la, i1 = 1.f / lb;
        int r0 = wr + 16 + g, r1 = wr + 16 + g + 8;
        #pragma unroll
        for (int nf = 0; nf < 16; nf++) {
            int c = nf * 8 + 2 * tg;
            float2 q0 = __half22float2(*(const __half2*)(qp + (long)r0 * DMODEL + c));
            float2 q1 = __half22float2(*(const __half2*)(qp + (long)r1 * DMODEL + c));
            *(float2*)(op + (long)r0 * DMODEL + c) =
                make_float2(q0.x + o1[nf][0] * i0, q0.y + o1[nf][1] * i0);
            *(float2*)(op + (long)r1 * DMODEL + c) =
                make_float2(q1.x + o1[nf][2] * i1, q1.y + o1[nf][3] * i1);
        }
    }
}

// ---------------------------------------------------------------------------
// LayerNorm (rows of 1024). WH: also emit half copy.
// ---------------------------------------------------------------------------
template<bool WH>
__global__ __launch_bounds__(256)
void ln_kernel(const float* __restrict__ X, float* __restrict__ Y,
               __half* __restrict__ Yh,
               const float* __restrict__ gam, const float* __restrict__ bet)
{
    const float* x = X + (size_t)blockIdx.x * DMODEL;
    float*       y = Y + (size_t)blockIdx.x * DMODEL;
    __half*      yh = WH ? (Yh + (size_t)blockIdx.x * DMODEL) : nullptr;
    const int tid = threadIdx.x;
    float v[4];
    float s = 0.f, sq = 0.f;
    #pragma unroll
    for (int i = 0; i < 4; i++) {
        v[i] = x[i * 256 + tid];
        s  += v[i];
        sq += v[i] * v[i];
    }
    s  = warpSum(s);
    sq = warpSum(sq);
    __shared__ float a1[8], a2[8];
    if ((tid & 31) == 0) { a1[tid >> 5] = s; a2[tid >> 5] = sq; }
    __syncthreads();
    float S1 = ((a1[0] + a1[1]) + (a1[2] + a1[3])) + ((a1[4] + a1[5]) + (a1[6] + a1[7]));
    float S2 = ((a2[0] + a2[1]) + (a2[2] + a2[3])) + ((a2[4] + a2[5]) + (a2[6] + a2[7]));
    float mu  = S1 * (1.f / DMODEL);
    float var = S2 * (1.f / DMODEL) - mu * mu;
    float rs  = rsqrtf(var + 1e-5f);
    #pragma unroll
    for (int i = 0; i < 4; i++) {
        int c = i * 256 + tid;
        float r = (v[i] - mu) * rs * gam[c] + bet[c];
        y[c] = r;
        if (WH) yh[c] = __float2half_rn(r);
    }
}

// ---------------------------------------------------------------------------
extern "C" void kernel_launch(void* const* d_in, const int* in_sizes, int n_in,
                              void* d_out, int out_size)
{
    (void)in_sizes; (void)n_in; (void)out_size;
    const float* Q  = (const float*)d_in[0];
    const float* K_ = (const float*)d_in[1];
    const float* Wq = (const float*)d_in[2];
    const float* bq = (const float*)d_in[3];
    const float* Wk = (const float*)d_in[4];
    const float* bk = (const float*)d_in[5];
    const float* Wv = (const float*)d_in[6];
    const float* bv = (const float*)d_in[7];
    const float* Wo = (const float*)d_in[8];
    const float* bo = (const float*)d_in[9];
    const float* g0 = (const float*)d_in[10];
    const float* b0 = (const float*)d_in[11];
    const float* g1 = (const float*)d_in[12];
    const float* b1 = (const float*)d_in[13];
    float* out = (float*)d_out;

    __half *Qh, *Kh, *Wqh, *Wkh, *Wvh, *Woh, *qh, *kh, *vh, *x0h;
    float *att, *x0f;
    cudaGetSymbolAddress((void**)&Qh,  g_Qh);
    cudaGetSymbolAddress((void**)&Kh,  g_Kh);
    cudaGetSymbolAddress((void**)&Wqh, g_Wqh);
    cudaGetSymbolAddress((void**)&Wkh, g_Wkh);
    cudaGetSymbolAddress((void**)&Wvh, g_Wvh);
    cudaGetSymbolAddress((void**)&Woh, g_Woh);
    cudaGetSymbolAddress((void**)&qh,  g_qh);
    cudaGetSymbolAddress((void**)&kh,  g_kh);
    cudaGetSymbolAddress((void**)&vh,  g_vh);
    cudaGetSymbolAddress((void**)&x0h, g_x0h);
    cudaGetSymbolAddress((void**)&att, g_att);
    cudaGetSymbolAddress((void**)&x0f, g_x0f);

    const int GEMM_SMEM  = 65536;
    const int FLASH_SMEM = 208896;
    cudaFuncSetAttribute(gemm_h<0>, cudaFuncAttributeMaxDynamicSharedMemorySize, GEMM_SMEM);
    cudaFuncSetAttribute(gemm_h<3>, cudaFuncAttributeMaxDynamicSharedMemorySize, GEMM_SMEM);
    cudaFuncSetAttribute(flash_h,   cudaFuncAttributeMaxDynamicSharedMemorySize, FLASH_SMEM);

    const int NA = NROWS * DMODEL;     // 8M
    const int NW = DMODEL * DMODEL;    // 1M

    ConvArgs cqk; cqk.s[0] = Q;  cqk.s[1] = K_; cqk.d[0] = Qh;  cqk.d[1] = Kh;
    cqk.s[2] = Q; cqk.s[3] = Q; cqk.d[2] = Qh; cqk.d[3] = Qh;
    conv_f2h<<<dim3(NA / 1024, 2), 256>>>(cqk, NA);
    ConvArgs cw;
    cw.s[0] = Wq; cw.s[1] = Wk; cw.s[2] = Wv; cw.s[3] = Wo;
    cw.d[0] = Wqh; cw.d[1] = Wkh; cw.d[2] = Wvh; cw.d[3] = Woh;
    conv_f2h<<<dim3(NW / 1024, 4), 256>>>(cw, NW);

    GemmArgs gaP = {};
    gaP.A[0] = Qh; gaP.A[1] = Kh; gaP.A[2] = Kh;
    gaP.B[0] = Wqh; gaP.B[1] = Wkh; gaP.B[2] = Wvh;
    gaP.C[0] = qh; gaP.C[1] = kh; gaP.C[2] = vh;
    gaP.bias[0] = bq; gaP.bias[1] = bk; gaP.bias[2] = bv;
    dim3 blk(256);
    gemm_h<0><<<dim3(DMODEL / 128, NROWS / 128, 3), blk, GEMM_SMEM>>>(gaP);

    dim3 gf(NKEYS / 256, NBH);                   // (8, 32)
    flash_h<<<gf, blk, FLASH_SMEM>>>(qh, kh, vh, att);

    ln_kernel<true><<<NROWS, 256>>>(att, x0f, x0h, g0, b0);

    GemmArgs gaO = {};
    gaO.A[0] = x0h; gaO.B[0] = Woh; gaO.C[0] = att; gaO.bias[0] = bo;
    gaO.Res = x0f;
    gemm_h<3><<<dim3(DMODEL / 128, NROWS / 128, 1), blk, GEMM_SMEM>>>(gaO);

    ln_kernel<false><<<NROWS, 256>>>(att, out, nullptr, g1, b1);
}

// round 12
// speedup vs baseline: 1.0571x; 1.0005x over previous
#include <cuda_runtime.h>
#include <cuda_fp16.h>
#include <cstdint>

#define NROWS   8192
#define DMODEL  1024
#define NKEYS   2048
#define NBH     32

__device__ __half g_Qh [NROWS * DMODEL];
__device__ __half g_Kh [NROWS * DMODEL];
__device__ __half g_Wqh[DMODEL * DMODEL];
__device__ __half g_Wkh[DMODEL * DMODEL];
__device__ __half g_Wvh[DMODEL * DMODEL];
__device__ __half g_Woh[DMODEL * DMODEL];
__device__ __half g_qh [NROWS * DMODEL];
__device__ __half g_kh [NROWS * DMODEL];
__device__ __half g_vh [NROWS * DMODEL];
__device__ __half g_x0h[NROWS * DMODEL];
__device__ float  g_att[NROWS * DMODEL];
__device__ float  g_x0f[NROWS * DMODEL];

__device__ __forceinline__ uint32_t h2u(__half2 h) {
    uint32_t u;
    asm("mov.b32 %0, %1;" : "=r"(u) : "r"(*(uint32_t*)&h));
    return u;
}
__device__ __forceinline__ float ex2(float x) {
    float y;
    asm("ex2.approx.f32 %0, %1;" : "=f"(y) : "f"(x));
    return y;
}
// packed half2 exp2: one MUFU op for two lanes
__device__ __forceinline__ uint32_t hex2(uint32_t x) {
    uint32_t y;
    asm("ex2.approx.f16x2 %0, %1;" : "=r"(y) : "r"(x));
    return y;
}
__device__ __forceinline__ void ldsm4(uint32_t a[4], uint32_t addr) {
    asm volatile("ldmatrix.sync.aligned.m8n8.x4.shared.b16 {%0,%1,%2,%3}, [%4];"
                 : "=r"(a[0]), "=r"(a[1]), "=r"(a[2]), "=r"(a[3]) : "r"(addr));
}
__device__ __forceinline__ void ldsm4t(uint32_t a[4], uint32_t addr) {
    asm volatile("ldmatrix.sync.aligned.m8n8.x4.trans.shared.b16 {%0,%1,%2,%3}, [%4];"
                 : "=r"(a[0]), "=r"(a[1]), "=r"(a[2]), "=r"(a[3]) : "r"(addr));
}
__device__ __forceinline__ void mma_h(float* c, const uint32_t a[4], uint32_t b0, uint32_t b1) {
    asm volatile("mma.sync.aligned.m16n8k16.row.col.f32.f16.f16.f32 "
                 "{%0,%1,%2,%3}, {%4,%5,%6,%7}, {%8,%9}, {%0,%1,%2,%3};"
                 : "+f"(c[0]), "+f"(c[1]), "+f"(c[2]), "+f"(c[3])
                 : "r"(a[0]), "r"(a[1]), "r"(a[2]), "r"(a[3]), "r"(b0), "r"(b1));
}
__device__ __forceinline__ void cp16(uint32_t dst, const void* src) {
    asm volatile("cp.async.ca.shared.global [%0], [%1], 16;\n" :: "r"(dst), "l"(src));
}
#define CP_COMMIT() asm volatile("cp.async.commit_group;\n")
#define CP_WAIT1()  asm volatile("cp.async.wait_group 1;\n")
#define CP_WAIT2()  asm volatile("cp.async.wait_group 2;\n")

__device__ __forceinline__ float warpSum(float v) {
    #pragma unroll
    for (int o = 16; o; o >>= 1) v += __shfl_xor_sync(0xFFFFFFFFu, v, o);
    return v;
}
__device__ __forceinline__ float quadMax(float v) {
    v = fmaxf(v, __shfl_xor_sync(0xFFFFFFFFu, v, 1));
    v = fmaxf(v, __shfl_xor_sync(0xFFFFFFFFu, v, 2));
    return v;
}

// ---------------- batched fp32 -> fp16 ----------------
struct ConvArgs { const float* s[4]; __half* d[4]; };

__global__ __launch_bounds__(256)
void conv_f2h(ConvArgs ca, int n)
{
    const float* s = ca.s[blockIdx.y];
    __half*      d = ca.d[blockIdx.y];
    int i = (blockIdx.x * 256 + threadIdx.x) * 4;
    if (i < n) {
        float4 v = *(const float4*)(s + i);
        __half2* o = (__half2*)(d + i);
        o[0] = __floats2half2_rn(v.x, v.y);
        o[1] = __floats2half2_rn(v.z, v.w);
    }
}

// ---------------------------------------------------------------------------
// fp16 GEMM C = epi(A @ B^T), batched over blockIdx.z (pointer arrays).
// (unchanged)
// ---------------------------------------------------------------------------
struct GemmArgs {
    const __half* A[3];
    const __half* B[3];
    void*         C[3];
    const float*  bias[3];
    const float*  Res;
};

template<int EPI>
__global__ __launch_bounds__(256, 2)
void gemm_h(GemmArgs ga)
{
    extern __shared__ char smc[];
    const uint32_t smA = (uint32_t)__cvta_generic_to_shared(smc);
    const uint32_t smB = smA + 32768;

    const int z = blockIdx.z;
    const __half* __restrict__ A = ga.A[z];
    const __half* __restrict__ B = ga.B[z];
    void* Cv = ga.C[z];
    const float* __restrict__ bias = ga.bias[z];
    const float* __restrict__ Res = ga.Res;

    const int m0 = blockIdx.y * 128, n0 = blockIdx.x * 128;
    const int tid = threadIdx.x, warp = tid >> 5, lane = tid & 31;
    const int wm = (warp >> 2) * 64, wn = (warp & 3) * 32;
    const int g = lane >> 2, tg = lane & 3;
    const uint32_t l7 = lane & 7, lb3 = (lane >> 3) & 1, lb4 = (uint32_t)lane >> 4;

    float acc[4][4][4];
    #pragma unroll
    for (int i = 0; i < 4; i++)
        #pragma unroll
        for (int j = 0; j < 4; j++)
            #pragma unroll
            for (int e = 0; e < 4; e++) acc[i][j][e] = 0.f;

    auto stage = [&](int s, int k0) {
        #pragma unroll
        for (int i = 0; i < 4; i++) {
            int idx = tid + i * 256;
            uint32_t row = idx >> 3, c = idx & 7;
            uint32_t d = s * 16384 + row * 128 + ((c ^ (row & 7)) * 16);
            cp16(smA + d, A + (long)(m0 + row) * DMODEL + k0 + c * 8);
            cp16(smB + d, B + (long)(n0 + row) * DMODEL + k0 + c * 8);
        }
    };
    stage(0, 0);  CP_COMMIT();
    stage(1, 64); CP_COMMIT();

    for (int kt = 0; kt < 16; kt++) {
        CP_WAIT1();
        __syncthreads();
        const uint32_t sa = smA + (kt & 1) * 16384;
        const uint32_t sb = smB + (kt & 1) * 16384;
        #pragma unroll
        for (int ks = 0; ks < 4; ks++) {
            uint32_t af[4][4], bf[2][4];
            #pragma unroll
            for (int mi = 0; mi < 4; mi++) {
                uint32_t row = wm + mi * 16 + lb3 * 8 + l7;
                uint32_t cc  = ks * 2 + lb4;
                ldsm4(af[mi], sa + row * 128 + ((cc ^ (row & 7)) * 16));
            }
            #pragma unroll
            for (int nj = 0; nj < 2; nj++) {
                uint32_t row = wn + nj * 16 + lb4 * 8 + l7;
                uint32_t cc  = ks * 2 + lb3;
                ldsm4(bf[nj], sb + row * 128 + ((cc ^ (row & 7)) * 16));
            }
            #pragma unroll
            for (int mi = 0; mi < 4; mi++)
                #pragma unroll
                for (int nf = 0; nf < 4; nf++)
                    mma_h(acc[mi][nf], af[mi], bf[nf >> 1][(nf & 1) * 2],
                          bf[nf >> 1][(nf & 1) * 2 + 1]);
        }
        __syncthreads();
        if (kt < 14) stage(kt & 1, (kt + 2) * 64);
        CP_COMMIT();
    }

    #pragma unroll
    for (int mi = 0; mi < 4; mi++) {
        #pragma unroll
        for (int nf = 0; nf < 4; nf++) {
            int r = m0 + wm + mi * 16 + g;
            int c = n0 + wn + nf * 8 + 2 * tg;
            float b0 = bias[c], b1 = bias[c + 1];
            if (EPI == 0) {
                __half* C = (__half*)Cv;
                *(__half2*)(C + (long)r * DMODEL + c) =
                    __floats2half2_rn(acc[mi][nf][0] + b0, acc[mi][nf][1] + b1);
                *(__half2*)(C + (long)(r + 8) * DMODEL + c) =
                    __floats2half2_rn(acc[mi][nf][2] + b0, acc[mi][nf][3] + b1);
            } else {
                float* C = (float*)Cv;
                float2 v0, v1;
                v0.x = fmaxf(acc[mi][nf][0] + b0, 0.f) + Res[(long)r * DMODEL + c];
                v0.y = fmaxf(acc[mi][nf][1] + b1, 0.f) + Res[(long)r * DMODEL + c + 1];
                v1.x = fmaxf(acc[mi][nf][2] + b0, 0.f) + Res[(long)(r + 8) * DMODEL + c];
                v1.y = fmaxf(acc[mi][nf][3] + b1, 0.f) + Res[(long)(r + 8) * DMODEL + c + 1];
                *(float2*)(C + (long)r * DMODEL + c) = v0;
                *(float2*)(C + (long)(r + 8) * DMODEL + c) = v1;
            }
        }
    }
}

// ---------------------------------------------------------------------------
// fp16 flash, BM=256: CTA = one (b,h) x 256 q-rows; warp owns 32 rows.
// Softmax: packed f16x2 ex2 (halves MUFU), row-sum l via ones-B MMA,
// warp-uniform rescale skip. 4-slot K/V ring, prefetch distance 3.
// smem: Q 256x272 [0,69632) | K 4x17408 [69632,139264) | V 4x17408 [139264,208896)
// ---------------------------------------------------------------------------
__global__ __launch_bounds__(256, 1)
void flash_h(const __half* __restrict__ qb, const __half* __restrict__ kb,
             const __half* __restrict__ vb, float* __restrict__ att)
{
    extern __shared__ char smc[];
    const uint32_t smQ = (uint32_t)__cvta_generic_to_shared(smc);
    const uint32_t smK = smQ + 69632;
    const uint32_t smV = smQ + 139264;

    const int bh = blockIdx.y, zb = bh >> 3, zh = bh & 7;
    const long base = (long)zb * (NKEYS * DMODEL) + zh * 128;
    const __half* qp = qb + base + (long)blockIdx.x * 256 * DMODEL;
    const __half* kp = kb + base;
    const __half* vp = vb + base;
    float*        op = att + base + (long)blockIdx.x * 256 * DMODEL;

    const int tid = threadIdx.x, warp = tid >> 5, lane = tid & 31;
    const int g = lane >> 2, tg = lane & 3;
    const int wr = warp * 32;
    const uint32_t l7 = lane & 7, lb3 = (lane >> 3) & 1, lb4 = (uint32_t)lane >> 4;
    const float isq2 = 0.088388347648318447f * 1.44269504088896341f;  // log2e/sqrt(d)
    const uint32_t ONESH2 = 0x3C003C00u;   // half2(1,1)

    // stage Q: 256 rows x 16 chunks (commit group 0, with KV tile 0)
    #pragma unroll
    for (int i = 0; i < 16; i++) {
        int idx = tid + i * 256;
        uint32_t r = idx >> 4, c = idx & 15;
        cp16(smQ + r * 272 + c * 16, qp + (long)r * DMODEL + c * 8);
    }
    auto stage = [&](int s, int jt) {
        #pragma unroll
        for (int i = 0; i < 4; i++) {
            int idx = tid + i * 256;
            uint32_t r = idx >> 4, c = idx & 15;
            const long go = (long)(jt * 64 + r) * DMODEL + c * 8;
            uint32_t d = s * 17408 + r * 272 + c * 16;
            cp16(smK + d, kp + go);
            cp16(smV + d, vp + go);
        }
    };
    stage(0, 0); CP_COMMIT();
    stage(1, 1); CP_COMMIT();
    stage(2, 2); CP_COMMIT();

    CP_WAIT2();
    __syncthreads();

    float o0[16][4], o1[16][4];
    #pragma unroll
    for (int f = 0; f < 16; f++)
        #pragma unroll
        for (int e = 0; e < 4; e++) { o0[f][e] = 0.f; o1[f][e] = 0.f; }
    float m00 = -1e30f, m01 = -1e30f, l00 = 0.f, l01 = 0.f;   // rt0 rows g, g+8
    float m10 = -1e30f, m11 = -1e30f, l10 = 0.f, l11 = 0.f;   // rt1

    const uint32_t qrow0 = wr + lb3 * 8 + l7;
    const uint32_t qrow1 = qrow0 + 16;

    // softmax for one row-tile: s (f32) -> ah (half2 P), l update, o rescale
    auto softmax = [&](float (&s)[8][4], float& m0, float& m1, float& l0, float& l1,
                       uint32_t (&ah)[8][2], float (&o)[16][4]) {
        float tm0 = -1e30f, tm1 = -1e30f;
        #pragma unroll
        for (int t = 0; t < 8; t++) {
            s[t][0] *= isq2; s[t][1] *= isq2; s[t][2] *= isq2; s[t][3] *= isq2;
            tm0 = fmaxf(tm0, fmaxf(s[t][0], s[t][1]));
            tm1 = fmaxf(tm1, fmaxf(s[t][2], s[t][3]));
        }
        tm0 = quadMax(tm0); tm1 = quadMax(tm1);
        float mn0 = fmaxf(m0, tm0), mn1 = fmaxf(m1, tm1);
        bool upd = (mn0 != m0) || (mn1 != m1);
        bool any = __any_sync(0xFFFFFFFFu, upd);

        // P = 2^(s - mn) in packed half2 (one MUFU per 2 values)
        #pragma unroll
        for (int t = 0; t < 8; t++) {
            ah[t][0] = hex2(h2u(__floats2half2_rn(s[t][0] - mn0, s[t][1] - mn0)));
            ah[t][1] = hex2(h2u(__floats2half2_rn(s[t][2] - mn1, s[t][3] - mn1)));
        }

        // row sums via ones-B MMA (fp32 accumulation of the exact same fp16 P)
        float ls[4] = {0.f, 0.f, 0.f, 0.f};
        #pragma unroll
        for (int kv = 0; kv < 4; kv++) {
            uint32_t pa[4] = { ah[2*kv][0], ah[2*kv][1], ah[2*kv+1][0], ah[2*kv+1][1] };
            mma_h(ls, pa, ONESH2, ONESH2);
        }

        if (any) {
            float sc0 = ex2(m0 - mn0), sc1 = ex2(m1 - mn1);
            m0 = mn0; m1 = mn1;
            l0 = l0 * sc0 + ls[0];
            l1 = l1 * sc1 + ls[2];
            #pragma unroll
            for (int f = 0; f < 16; f++) {
                o[f][0] *= sc0; o[f][1] *= sc0;
                o[f][2] *= sc1; o[f][3] *= sc1;
            }
        } else {
            l0 += ls[0];
            l1 += ls[2];
        }
    };

    for (int j = 0; j < 32; j++) {
        if (j) { CP_WAIT2(); __syncthreads(); }
        const uint32_t sk = smK + (j & 3) * 17408;
        const uint32_t sv = smV + (j & 3) * 17408;

        if (j + 3 < 32) stage((j + 3) & 3, j + 3);
        CP_COMMIT();

        // ---- S = Q K^T for both row-tiles; K fragment loaded once ----
        float s0[8][4], s1[8][4];
        #pragma unroll
        for (int t = 0; t < 8; t++)
            #pragma unroll
            for (int e = 0; e < 4; e++) { s0[t][e] = 0.f; s1[t][e] = 0.f; }
        #pragma unroll
        for (int ks = 0; ks < 8; ks++) {
            uint32_t qa0[4], qa1[4];
            ldsm4(qa0, smQ + qrow0 * 272 + (ks * 2 + lb4) * 16);
            ldsm4(qa1, smQ + qrow1 * 272 + (ks * 2 + lb4) * 16);
            #pragma unroll
            for (int nt = 0; nt < 4; nt++) {
                uint32_t kf[4];
                uint32_t row = nt * 16 + lb4 * 8 + l7;
                ldsm4(kf, sk + row * 272 + (ks * 2 + lb3) * 16);
                mma_h(s0[nt * 2],     qa0, kf[0], kf[1]);
                mma_h(s0[nt * 2 + 1], qa0, kf[2], kf[3]);
                mma_h(s1[nt * 2],     qa1, kf[0], kf[1]);
                mma_h(s1[nt * 2 + 1], qa1, kf[2], kf[3]);
            }
        }

        uint32_t ah0[8][2], ah1[8][2];
        softmax(s0, m00, m01, l00, l01, ah0, o0);
        softmax(s1, m10, m11, l10, l11, ah1, o1);

        // ---- O += P V for both row-tiles; V fragment loaded once ----
        #pragma unroll
        for (int kv = 0; kv < 4; kv++) {
            uint32_t pa0[4] = { ah0[2*kv][0], ah0[2*kv][1], ah0[2*kv+1][0], ah0[2*kv+1][1] };
            uint32_t pa1[4] = { ah1[2*kv][0], ah1[2*kv][1], ah1[2*kv+1][0], ah1[2*kv+1][1] };
            uint32_t vrow = kv * 16 + lb3 * 8 + l7;
            #pragma unroll
            for (int nt2 = 0; nt2 < 8; nt2++) {
                uint32_t vf[4];
                ldsm4t(vf, sv + vrow * 272 + (nt2 * 2 + lb4) * 16);
                mma_h(o0[nt2 * 2],     pa0, vf[0], vf[1]);
                mma_h(o0[nt2 * 2 + 1], pa0, vf[2], vf[3]);
                mma_h(o1[nt2 * 2],     pa1, vf[0], vf[1]);
                mma_h(o1[nt2 * 2 + 1], pa1, vf[2], vf[3]);
            }
        }
    }

    // ---- epilogue: out = q + O / l (l already full row sums; quad-uniform) ----
    {
        float i0 = 1.f / l00, i1 = 1.f / l01;
        int r0 = wr + g, r1 = wr + g + 8;
        #pragma unroll
        for (int nf = 0; nf < 16; nf++) {
            int c = nf * 8 + 2 * tg;
            float2 q0 = __half22float2(*(const __half2*)(qp + (long)r0 * DMODEL + c));
            float2 q1 = __half22float2(*(const __half2*)(qp + (long)r1 * DMODEL + c));
            *(float2*)(op + (long)r0 * DMODEL + c) =
                make_float2(q0.x + o0[nf][0] * i0, q0.y + o0[nf][1] * i0);
            *(float2*)(op + (long)r1 * DMODEL + c) =
                make_float2(q1.x + o0[nf][2] * i1, q1.y + o0[nf][3] * i1);
        }
    }
    {
        float i0 = 1.f / l10, i1 = 1.f / l11;
        int r0 = wr + 16 + g, r1 = wr + 16 + g + 8;
        #pragma unroll
        for (int nf = 0; nf < 16; nf++) {
            int c = nf * 8 + 2 * tg;
            float2 q0 = __half22float2(*(const __half2*)(qp + (long)r0 * DMODEL + c));
            float2 q1 = __half22float2(*(const __half2*)(qp + (long)r1 * DMODEL + c));
            *(float2*)(op + (long)r0 * DMODEL + c) =
                make_float2(q0.x + o1[nf][0] * i0, q0.y + o1[nf][1] * i0);
            *(float2*)(op + (long)r1 * DMODEL + c) =
                make_float2(q1.x + o1[nf][2] * i1, q1.y + o1[nf][3] * i1);
        }
    }
}

// ---------------------------------------------------------------------------
// LayerNorm (rows of 1024). WH: also emit half copy.
// ---------------------------------------------------------------------------
template<bool WH>
__global__ __launch_bounds__(256)
void ln_kernel(const float* __restrict__ X, float* __restrict__ Y,
               __half* __restrict__ Yh,
               const float* __restrict__ gam, const float* __restrict__ bet)
{
    const float* x = X + (size_t)blockIdx.x * DMODEL;
    float*       y = Y + (size_t)blockIdx.x * DMODEL;
    __half*      yh = WH ? (Yh + (size_t)blockIdx.x * DMODEL) : nullptr;
    const int tid = threadIdx.x;
    float v[4];
    float s = 0.f, sq = 0.f;
    #pragma unroll
    for (int i = 0; i < 4; i++) {
        v[i] = x[i * 256 + tid];
        s  += v[i];
        sq += v[i] * v[i];
    }
    s  = warpSum(s);
    sq = warpSum(sq);
    __shared__ float a1[8], a2[8];
    if ((tid & 31) == 0) { a1[tid >> 5] = s; a2[tid >> 5] = sq; }
    __syncthreads();
    float S1 = ((a1[0] + a1[1]) + (a1[2] + a1[3])) + ((a1[4] + a1[5]) + (a1[6] + a1[7]));
    float S2 = ((a2[0] + a2[1]) + (a2[2] + a2[3])) + ((a2[4] + a2[5]) + (a2[6] + a2[7]));
    float mu  = S1 * (1.f / DMODEL);
    float var = S2 * (1.f / DMODEL) - mu * mu;
    float rs  = rsqrtf(var + 1e-5f);
    #pragma unroll
    for (int i = 0; i < 4; i++) {
        int c = i * 256 + tid;
        float r = (v[i] - mu) * rs * gam[c] + bet[c];
        y[c] = r;
        if (WH) yh[c] = __float2half_rn(r);
    }
}

// ---------------------------------------------------------------------------
extern "C" void kernel_launch(void* const* d_in, const int* in_sizes, int n_in,
                              void* d_out, int out_size)
{
    (void)in_sizes; (void)n_in; (void)out_size;
    const float* Q  = (const float*)d_in[0];
    const float* K_ = (const float*)d_in[1];
    const float* Wq = (const float*)d_in[2];
    const float* bq = (const float*)d_in[3];
    const float* Wk = (const float*)d_in[4];
    const float* bk = (const float*)d_in[5];
    const float* Wv = (const float*)d_in[6];
    const float* bv = (const float*)d_in[7];
    const float* Wo = (const float*)d_in[8];
    const float* bo = (const float*)d_in[9];
    const float* g0 = (const float*)d_in[10];
    const float* b0 = (const float*)d_in[11];
    const float* g1 = (const float*)d_in[12];
    const float* b1 = (const float*)d_in[13];
    float* out = (float*)d_out;

    __half *Qh, *Kh, *Wqh, *Wkh, *Wvh, *Woh, *qh, *kh, *vh, *x0h;
    float *att, *x0f;
    cudaGetSymbolAddress((void**)&Qh,  g_Qh);
    cudaGetSymbolAddress((void**)&Kh,  g_Kh);
    cudaGetSymbolAddress((void**)&Wqh, g_Wqh);
    cudaGetSymbolAddress((void**)&Wkh, g_Wkh);
    cudaGetSymbolAddress((void**)&Wvh, g_Wvh);
    cudaGetSymbolAddress((void**)&Woh, g_Woh);
    cudaGetSymbolAddress((void**)&qh,  g_qh);
    cudaGetSymbolAddress((void**)&kh,  g_kh);
    cudaGetSymbolAddress((void**)&vh,  g_vh);
    cudaGetSymbolAddress((void**)&x0h, g_x0h);
    cudaGetSymbolAddress((void**)&att, g_att);
    cudaGetSymbolAddress((void**)&x0f, g_x0f);

    const int GEMM_SMEM  = 65536;
    const int FLASH_SMEM = 208896;
    cudaFuncSetAttribute(gemm_h<0>, cudaFuncAttributeMaxDynamicSharedMemorySize, GEMM_SMEM);
    cudaFuncSetAttribute(gemm_h<3>, cudaFuncAttributeMaxDynamicSharedMemorySize, GEMM_SMEM);
    cudaFuncSetAttribute(flash_h,   cudaFuncAttributeMaxDynamicSharedMemorySize, FLASH_SMEM);

    const int NA = NROWS * DMODEL;     // 8M
    const int NW = DMODEL * DMODEL;    // 1M

    ConvArgs cqk; cqk.s[0] = Q;  cqk.s[1] = K_; cqk.d[0] = Qh;  cqk.d[1] = Kh;
    cqk.s[2] = Q; cqk.s[3] = Q; cqk.d[2] = Qh; cqk.d[3] = Qh;
    conv_f2h<<<dim3(NA / 1024, 2), 256>>>(cqk, NA);
    ConvArgs cw;
    cw.s[0] = Wq; cw.s[1] = Wk; cw.s[2] = Wv; cw.s[3] = Wo;
    cw.d[0] = Wqh; cw.d[1] = Wkh; cw.d[2] = Wvh; cw.d[3] = Woh;
    conv_f2h<<<dim3(NW / 1024, 4), 256>>>(cw, NW);

    GemmArgs gaP = {};
    gaP.A[0] = Qh; gaP.A[1] = Kh; gaP.A[2] = Kh;
    gaP.B[0] = Wqh; gaP.B[1] = Wkh; gaP.B[2] = Wvh;
    gaP.C[0] = qh; gaP.C[1] = kh; gaP.C[2] = vh;
    gaP.bias[0] = bq; gaP.bias[1] = bk; gaP.bias[2] = bv;
    dim3 blk(256);
    gemm_h<0><<<dim3(DMODEL / 128, NROWS / 128, 3), blk, GEMM_SMEM>>>(gaP);

    dim3 gf(NKEYS / 256, NBH);                   // (8, 32)
    flash_h<<<gf, blk, FLASH_SMEM>>>(qh, kh, vh, att);

    ln_kernel<true><<<NROWS, 256>>>(att, x0f, x0h, g0, b0);

    GemmArgs gaO = {};
    gaO.A[0] = x0h; gaO.B[0] = Woh; gaO.C[0] = att; gaO.bias[0] = bo;
    gaO.Res = x0f;
    gemm_h<3><<<dim3(DMODEL / 128, NROWS / 128, 1), blk, GEMM_SMEM>>>(gaO);

    ln_kernel<false><<<NROWS, 256>>>(att, out, nullptr, g1, b1);
}